// round 2
// baseline (speedup 1.0000x reference)
#include <cuda_runtime.h>
#include <cstdint>

// Problem constants (deterministic from setup_inputs)
#define LL    320
#define DD    128
#define NBINS 32
#define EPSF  1e-8f

#define Z_ELEMS (LL*LL*DD)     // 13,107,200
#define P_ELEMS (3*LL*LL)      //    307,200
// output layout: [z | pxyz | cadistavg], all f32

// cadistavg tiling
#define TJ 16
#define TK 16
#define NT (LL/TJ)             // 20
#define C_BLOCKS (NT*NT)       // 400
#define Z_BLOCKS (LL*LL/8)     // 12800 (8 pairs per block, 32 lanes x float4 over D=128)
#define P_BLOCKS (P_ELEMS/4/256) // 300

__device__ __forceinline__ float fsqrt_approx(float x) {
    float y;
    asm("sqrt.approx.f32 %0, %1;" : "=f"(y) : "f"(x));
    return y;
}

__global__ __launch_bounds__(256)
void spired_fused(const int* __restrict__ residx,
                  const int* __restrict__ mask,        // bool delivered as int32
                  const float* __restrict__ emb,
                  const float4* __restrict__ pair4,
                  const float* __restrict__ predxyz,
                  const float* __restrict__ maskdiag,
                  float* __restrict__ out)
{
    const int blk = blockIdx.x;
    const int tid = threadIdx.x;

    if (blk < C_BLOCKS) {
        // ---- cadistavg[j,k] = (1/L) sum_i sqrt(sum_c (px[c,i,k]-px[c,i,j])^2 + eps)
        // px = predxyz * maskdiag, recomputed on the fly (L2-resident, 1.2MB)
        __shared__ float sK[3][16][TK];
        __shared__ float sJ[3][16][TJ];
        const int jt = (blk / NT) * TJ;
        const int kt = (blk % NT) * TK;
        const int tx = tid & 15;   // k within tile
        const int ty = tid >> 4;   // j within tile
        float acc = 0.0f;

        for (int i0 = 0; i0 < LL; i0 += 16) {
            // stage 3*16*16 elems for each of the two tiles: 3 loads/thread/tile
            #pragma unroll
            for (int q = 0; q < 3; q++) {
                int l  = q * 256 + tid;        // 0..767
                int c  = l >> 8;               // /256
                int r  = l & 255;
                int ii = r >> 4;
                int kk = r & 15;
                int gi = i0 + ii;
                float mdk = maskdiag[gi * LL + kt + kk];
                float mdj = maskdiag[gi * LL + jt + kk];
                sK[c][ii][kk] = predxyz[c * (LL*LL) + gi * LL + kt + kk] * mdk;
                sJ[c][ii][kk] = predxyz[c * (LL*LL) + gi * LL + jt + kk] * mdj;
            }
            __syncthreads();
            #pragma unroll
            for (int ii = 0; ii < 16; ii++) {
                float ax = sK[0][ii][tx], ay = sK[1][ii][tx], az = sK[2][ii][tx];
                float bx = sJ[0][ii][ty], by = sJ[1][ii][ty], bz = sJ[2][ii][ty];
                float dx = ax - bx, dy = ay - by, dz = az - bz;
                float s = fmaf(dx, dx, fmaf(dy, dy, fmaf(dz, dz, EPSF)));
                acc += fsqrt_approx(s);
            }
            __syncthreads();
        }
        out[Z_ELEMS + P_ELEMS + (jt + ty) * LL + (kt + tx)] = acc * (1.0f / LL);

    } else if (blk < C_BLOCKS + Z_BLOCKS) {
        // ---- z = pair_feats + emb_table[idx(i,j)]
        const int b    = blk - C_BLOCKS;
        const int lane = tid & 31;             // float4 slot over D=128
        const int p    = b * 8 + (tid >> 5);   // pair index (i*L + j)
        const int i    = p / LL;
        const int j    = p - i * LL;

        int m   = mask[i] & mask[j];
        int dif = residx[j] - residx[i];
        dif = min(max(dif, -NBINS), NBINS) + (NBINS + 1);
        const int idx = m ? dif : 0;

        const float4* e4 = (const float4*)emb;
        float4 ev = e4[idx * (DD / 4) + lane];
        float4 pv = pair4[(size_t)p * (DD / 4) + lane];
        float4 z  = make_float4(pv.x + ev.x, pv.y + ev.y, pv.z + ev.z, pv.w + ev.w);
        ((float4*)out)[(size_t)p * (DD / 4) + lane] = z;

    } else {
        // ---- pxyz = predxyz * maskdiag  (maskdiag broadcast over c)
        const int b = blk - C_BLOCKS - Z_BLOCKS;
        const int e = b * 256 + tid;           // float4 index, < 76800
        const float4* pr4 = (const float4*)predxyz;
        const float4* md4 = (const float4*)maskdiag;
        float4 pv = pr4[e];
        float4 mv = md4[e % (LL * LL / 4)];
        float4 r  = make_float4(pv.x * mv.x, pv.y * mv.y, pv.z * mv.z, pv.w * mv.w);
        ((float4*)(out + Z_ELEMS))[e] = r;
    }
}

extern "C" void kernel_launch(void* const* d_in, const int* in_sizes, int n_in,
                              void* d_out, int out_size) {
    const int*   residx   = (const int*)d_in[0];
    const int*   mask     = (const int*)d_in[1];
    const float* emb      = (const float*)d_in[2];
    const float4* pair4   = (const float4*)d_in[3];
    const float* predxyz  = (const float*)d_in[4];
    const float* maskdiag = (const float*)d_in[5];
    float*       out      = (float*)d_out;

    const int grid = C_BLOCKS + Z_BLOCKS + P_BLOCKS;  // 13500
    spired_fused<<<grid, 256>>>(residx, mask, emb, pair4, predxyz, maskdiag, out);
}